// round 1
// baseline (speedup 1.0000x reference)
#include <cuda_runtime.h>
#include <math.h>

#define NPIX 4140      // 46*90
#define CIN  256
#define HEADS 8
#define DHEAD 32
#define QT   256       // queries per attention block
#define KT   32        // key tile

// ---------------- scratch (no allocations allowed) ----------------
__device__ float g_Q[CIN * NPIX];
__device__ float g_K[CIN * NPIX];
__device__ float g_V[CIN * NPIX];
__device__ float g_O[CIN * NPIX];

// ============================================================================
// GEMM: Y[k][n] = sum_c W[k][c] * X[c][n] + b[k]
//   K = 256 (gridDim.y * 64), C = 256, N = 4140
//   sel: 0 -> Y = g_Q, 1 -> g_K, 2 -> g_V, 3 -> Y = Yext and X = g_O
// ============================================================================
__global__ __launch_bounds__(256)
void gemm_bias(const float* __restrict__ Xext,
               const float* __restrict__ W,
               const float* __restrict__ bias,
               float* __restrict__ Yext,
               int sel)
{
    const float* X = (sel == 3) ? g_O : Xext;
    float* Y;
    if      (sel == 0) Y = g_Q;
    else if (sel == 1) Y = g_K;
    else if (sel == 2) Y = g_V;
    else               Y = Yext;

    __shared__ float sW[16 * 65];   // [c][k], padded rows (stride 65)
    __shared__ float sX[16 * 64];   // [c][n]

    const int tid = threadIdx.x;
    const int k0 = blockIdx.y * 64;
    const int n0 = blockIdx.x * 64;
    const int ty = tid >> 4;        // 0..15 -> output k micro-row
    const int tx = tid & 15;        // 0..15 -> output n micro-col

    float acc[4][4];
    #pragma unroll
    for (int i = 0; i < 4; i++)
        #pragma unroll
        for (int j = 0; j < 4; j++) acc[i][j] = 0.f;

    for (int c0 = 0; c0 < CIN; c0 += 16) {
        // ---- load W tile 64x16 and X tile 16x64 ----
        #pragma unroll
        for (int r = 0; r < 4; r++) {
            int i = tid + 256 * r;
            // W: c fastest for coalescing
            int wc = i & 15, wk = i >> 4;
            sW[wc * 65 + wk] = W[(k0 + wk) * CIN + (c0 + wc)];
            // X: n fastest for coalescing
            int xn = i & 63, xc = i >> 6;
            int n = n0 + xn;
            sX[xc * 64 + xn] = (n < NPIX) ? X[(c0 + xc) * NPIX + n] : 0.f;
        }
        __syncthreads();

        #pragma unroll
        for (int cc = 0; cc < 16; cc++) {
            float a[4], bb[4];
            #pragma unroll
            for (int i = 0; i < 4; i++) a[i]  = sW[cc * 65 + ty * 4 + i];
            #pragma unroll
            for (int j = 0; j < 4; j++) bb[j] = sX[cc * 64 + tx * 4 + j];
            #pragma unroll
            for (int i = 0; i < 4; i++)
                #pragma unroll
                for (int j = 0; j < 4; j++)
                    acc[i][j] += a[i] * bb[j];
        }
        __syncthreads();
    }

    #pragma unroll
    for (int i = 0; i < 4; i++) {
        int k = k0 + ty * 4 + i;
        float bv = bias[k];
        #pragma unroll
        for (int j = 0; j < 4; j++) {
            int n = n0 + tx * 4 + j;
            if (n < NPIX) Y[k * NPIX + n] = acc[i][j] + bv;
        }
    }
}

// ============================================================================
// Fused flash attention (per-thread online softmax, one query per thread)
//   Q/K/V in [c][n] layout with c = head*32 + d.
//   scores = (q . k) / sqrt(32) + log_qw[m]; softmax over m; out = P V.
//   Output O in [c][n] layout (ready for the projection GEMM).
// ============================================================================
__global__ __launch_bounds__(256)
void attn_kernel(const float* __restrict__ logqw)
{
    __shared__ float sK[DHEAD * KT];   // [d][j]
    __shared__ float sV[DHEAD * KT];   // [d][j]
    __shared__ float sL[KT];

    const int h   = blockIdx.y;
    const int n0  = blockIdx.x * QT;
    const int tid = threadIdx.x;
    const int n   = n0 + tid;
    const bool valid = (n < NPIX);
    const int nc = valid ? n : (NPIX - 1);

    const float scale = 0.17677669529663687f;  // 1/sqrt(32)

    float q[DHEAD];
    #pragma unroll
    for (int d = 0; d < DHEAD; d++)
        q[d] = g_Q[(h * DHEAD + d) * NPIX + nc] * scale;

    float o[DHEAD];
    #pragma unroll
    for (int d = 0; d < DHEAD; d++) o[d] = 0.f;

    float mrun = -1e30f;
    float lsum = 0.f;

    for (int m0 = 0; m0 < NPIX; m0 += KT) {
        // ---- cooperative tile load: 2 * 32x32 floats + 32 bias ----
        #pragma unroll
        for (int r = 0; r < 4; r++) {
            int idx = tid + 256 * r;            // 0..1023
            int j = idx & (KT - 1);
            int d = idx >> 5;
            int mm = m0 + j;
            float kv = 0.f, vv = 0.f;
            if (mm < NPIX) {
                kv = g_K[(h * DHEAD + d) * NPIX + mm];
                vv = g_V[(h * DHEAD + d) * NPIX + mm];
            }
            sK[d * KT + j] = kv;
            sV[d * KT + j] = vv;
        }
        if (tid < KT) {
            int mm = m0 + tid;
            sL[tid] = (mm < NPIX) ? logqw[mm] : -1e30f;
        }
        __syncthreads();

        // ---- scores: s[j] = q . K[:,j] + logqw[j] ----
        float s[KT];
        #pragma unroll
        for (int j = 0; j < KT; j++) s[j] = sL[j];
        #pragma unroll
        for (int d = 0; d < DHEAD; d++) {
            float qd = q[d];
            #pragma unroll
            for (int j = 0; j < KT; j++)
                s[j] += qd * sK[d * KT + j];
        }

        float mt = mrun;
        #pragma unroll
        for (int j = 0; j < KT; j++) mt = fmaxf(mt, s[j]);

        float corr = __expf(mrun - mt);
        lsum *= corr;
        #pragma unroll
        for (int j = 0; j < KT; j++) {
            s[j] = __expf(s[j] - mt);      // reuse s as p
            lsum += s[j];
        }
        #pragma unroll
        for (int d = 0; d < DHEAD; d++) {
            float od = o[d] * corr;
            #pragma unroll
            for (int j = 0; j < KT; j++)
                od += s[j] * sV[d * KT + j];
            o[d] = od;
        }
        mrun = mt;
        __syncthreads();
    }

    if (valid) {
        float inv = 1.f / lsum;
        #pragma unroll
        for (int d = 0; d < DHEAD; d++)
            g_O[(h * DHEAD + d) * NPIX + n] = o[d] * inv;
    }
}

// ============================================================================
extern "C" void kernel_launch(void* const* d_in, const int* in_sizes, int n_in,
                              void* d_out, int out_size)
{
    const float* query = (const float*)d_in[0];
    const float* q_w   = (const float*)d_in[1];
    const float* q_b   = (const float*)d_in[2];
    const float* k_w   = (const float*)d_in[3];
    const float* k_b   = (const float*)d_in[4];
    const float* v_w   = (const float*)d_in[5];
    const float* v_b   = (const float*)d_in[6];
    const float* p_w   = (const float*)d_in[7];
    const float* p_b   = (const float*)d_in[8];
    const float* lqw   = (const float*)d_in[9];
    float* out = (float*)d_out;

    dim3 gb((NPIX + 63) / 64, 4, 1);   // 65 x 4

    gemm_bias<<<gb, 256>>>(query, q_w, q_b, nullptr, 0);   // -> g_Q
    gemm_bias<<<gb, 256>>>(query, k_w, k_b, nullptr, 1);   // -> g_K
    gemm_bias<<<gb, 256>>>(query, v_w, v_b, nullptr, 2);   // -> g_V

    dim3 ga((NPIX + QT - 1) / QT, HEADS, 1);               // 17 x 8
    attn_kernel<<<ga, 256>>>(lqw);                         // -> g_O

    gemm_bias<<<gb, 256>>>(nullptr, p_w, p_b, out, 3);     // g_O -> out
}